// round 7
// baseline (speedup 1.0000x reference)
#include <cuda_runtime.h>
#include <cuda_fp16.h>
#include <math.h>
#include <stdint.h>

#define N_ROIS 2000
#define MPAD   2048
#define IN_F   12544
#define REP    1024
#define NHEAD  512
#define NCLS   91
#define NC1    90
#define NPAD   2048
#define NEGV   (-1e10f)
#define BBOX_CLIP_F 4.135166556742356f
#define MAXDET 100
#define INV2048 4.8828125e-4f

// ======================= static scratch (no allocs; zero-initialized) =======================
__device__ __half gA_hi[MPAD * IN_F];
__device__ __half gA_lo[MPAD * IN_F];
__device__ __half gW1_hi[REP * IN_F];
__device__ __half gW1_lo[REP * IN_F];
__device__ __half gW2_hi[REP * REP];
__device__ __half gW2_lo[REP * REP];
__device__ __half gWh_hi[NHEAD * REP];
__device__ __half gWh_lo[NHEAD * REP];
__device__ __half gH1_hi[MPAD * REP];
__device__ __half gH1_lo[MPAD * REP];
__device__ __half gH2_hi[MPAD * REP];
__device__ __half gH2_lo[MPAD * REP];
__device__ float gBiasH[NHEAD];
__device__ float g_comb[N_ROIS * NHEAD];     // logits cols 0..90, breg cols 92+4c
__device__ float g_scores[N_ROIS * NCLS];
__device__ unsigned long long g_surv[NC1 * MAXDET];
__device__ int g_snum[NC1];

// ======================= helpers =======================
__device__ __forceinline__ uint32_t s2u(const void* p) {
    uint32_t a;
    asm("{ .reg .u64 t; cvta.to.shared.u64 t, %1; cvt.u32.u64 %0, t; }" : "=r"(a) : "l"(p));
    return a;
}
__device__ __forceinline__ void ldm4(uint32_t* r, uint32_t addr) {
    asm volatile("ldmatrix.sync.aligned.m8n8.x4.shared.b16 {%0,%1,%2,%3}, [%4];"
                 : "=r"(r[0]), "=r"(r[1]), "=r"(r[2]), "=r"(r[3]) : "r"(addr));
}
__device__ __forceinline__ void mma_f16(float* d, const uint32_t* a, const uint32_t* b) {
    asm volatile(
        "mma.sync.aligned.m16n8k16.row.col.f32.f16.f16.f32 "
        "{%0,%1,%2,%3}, {%4,%5,%6,%7}, {%8,%9}, {%0,%1,%2,%3};"
        : "+f"(d[0]), "+f"(d[1]), "+f"(d[2]), "+f"(d[3])
        : "r"(a[0]), "r"(a[1]), "r"(a[2]), "r"(a[3]), "r"(b[0]), "r"(b[1]));
}
// fp16-accumulator MMA (hypothesis: 2x rate of fp32-acc on sm_103a legacy pipe)
__device__ __forceinline__ void mma_f16acc(uint32_t* d, const uint32_t* a, const uint32_t* b) {
    asm volatile(
        "mma.sync.aligned.m16n8k16.row.col.f16.f16.f16.f16 "
        "{%0,%1}, {%2,%3,%4,%5}, {%6,%7}, {%0,%1};"
        : "+r"(d[0]), "+r"(d[1])
        : "r"(a[0]), "r"(a[1]), "r"(a[2]), "r"(a[3]), "r"(b[0]), "r"(b[1]));
}
__device__ __forceinline__ void split2(float x, __half& h, __half& l) {
    h = __float2half_rn(x);
    float r = x - __half2float(h);
    l = __float2half_rn(r * 2048.0f);
}
__device__ __forceinline__ void decode_one(
    int n, int c, const float* __restrict__ P, float Wim, float Him,
    float& x1, float& y1, float& x2, float& y2)
{
    const float4 p = *reinterpret_cast<const float4*>(&P[n * 4]);
    const float pw = p.z - p.x;
    const float ph = p.w - p.y;
    const float pcx = p.x + 0.5f * pw;
    const float pcy = p.y + 0.5f * ph;
    const float4 r = *reinterpret_cast<const float4*>(&g_comb[(size_t)n * NHEAD + 92 + c * 4]);
    const float dx = r.x / 10.0f;
    const float dy = r.y / 10.0f;
    const float dw = fminf(r.z / 5.0f, BBOX_CLIP_F);
    const float dh = fminf(r.w / 5.0f, BBOX_CLIP_F);
    const float cx = dx * pw + pcx;
    const float cy = dy * ph + pcy;
    const float w = expf(dw) * pw;
    const float hh = expf(dh) * ph;
    x1 = fminf(fmaxf(cx - 0.5f * w, 0.f), Wim);
    y1 = fminf(fmaxf(cy - 0.5f * hh, 0.f), Him);
    x2 = fminf(fmaxf(cx + 0.5f * w, 0.f), Wim);
    y2 = fminf(fmaxf(cy + 0.5f * hh, 0.f), Him);
}

// ======================= pre-pass kernels =======================
__global__ void split_X(const float* __restrict__ X) {
    const int idx = blockIdx.x * 256 + threadIdx.x;   // one float4
    if (idx >= N_ROIS * IN_F / 4) return;
    const size_t e = (size_t)idx * 4;
    const float4 v = *(const float4*)(X + e);
    __half h0, l0, h1, l1, h2, l2, h3, l3;
    split2(v.x, h0, l0); split2(v.y, h1, l1);
    split2(v.z, h2, l2); split2(v.w, h3, l3);
    __half2 t;
    t.x = h0; t.y = h1; *(__half2*)(gA_hi + e) = t;
    t.x = h2; t.y = h3; *(__half2*)(gA_hi + e + 2) = t;
    t.x = l0; t.y = l1; *(__half2*)(gA_lo + e) = t;
    t.x = l2; t.y = l3; *(__half2*)(gA_lo + e + 2) = t;
}

// transpose + split: W [K x N] fp32 -> out [N x K] fp16 x2
__global__ void tsplitW(const float* __restrict__ W,
                        __half* __restrict__ Oh, __half* __restrict__ Ol, int K, int N) {
    __shared__ float t[32][33];
    const int k0 = blockIdx.x * 32, n0 = blockIdx.y * 32;
    const int tx = threadIdx.x, ty = threadIdx.y;
#pragma unroll
    for (int i = 0; i < 4; ++i)
        t[ty + 8 * i][tx] = W[(size_t)(k0 + ty + 8 * i) * N + n0 + tx];
    __syncthreads();
#pragma unroll
    for (int i = 0; i < 4; ++i) {
        const float v = t[tx][ty + 8 * i];
        __half h, l;
        split2(v, h, l);
        const size_t o = (size_t)(n0 + ty + 8 * i) * K + k0 + tx;
        Oh[o] = h; Ol[o] = l;
    }
}

__global__ void build_head(const float* __restrict__ Wc, const float* __restrict__ Wr) {
    const int n = blockIdx.x;
    const int k = blockIdx.y * 256 + threadIdx.x;
    float v = 0.f;
    if (n < NCLS) v = Wc[(size_t)k * NCLS + n];
    else if (n >= 92 && n < 92 + 4 * NCLS) v = Wr[(size_t)k * (4 * NCLS) + (n - 92)];
    __half h, l;
    split2(v, h, l);
    const size_t o = (size_t)n * REP + k;
    gWh_hi[o] = h; gWh_lo[o] = l;
}

__global__ void build_bias(const float* __restrict__ bc, const float* __restrict__ br) {
    const int c = blockIdx.x * 256 + threadIdx.x;
    if (c >= NHEAD) return;
    float v = 0.f;
    if (c < NCLS) v = bc[c];
    else if (c >= 92 && c < 92 + 4 * NCLS) v = br[c - 92];
    gBiasH[c] = v;
}

// ======================= HMMA GEMM (BN=128) =======================
// C[M,N] = A[M,K] @ B[N,K]^T, fp32-equivalent via fp16 2-way split.
// Main product h*h: fp32-acc MMA. Cross products h*l + l*h: fp16-acc MMA
// (windowed over one 32-k stage, spilled into accM with *2^-11).
#define STAGE_B 32768
#define NSTAGE 4
#define SMEM_GEMM (NSTAGE * STAGE_B)

__global__ void __launch_bounds__(256, 1) hgemm(
    const __half* __restrict__ Ah, const __half* __restrict__ Al,
    const __half* __restrict__ Bh, const __half* __restrict__ Bl,
    const float* __restrict__ bias, int K, int Mreal, int mode,
    float* __restrict__ C, int ldc,
    __half* __restrict__ Oh, __half* __restrict__ Ol, int ldo)
{
    extern __shared__ __align__(16) char smem[];
    const uint32_t sb = s2u(smem);
    const int tid = threadIdx.x;
    const int lane = tid & 31, wid = tid >> 5;
    const int wm = wid & 1, wn = wid >> 1;           // warp tile: 64x32
    const int bm = blockIdx.y * 128, bn = blockIdx.x * 128;
    const int niter = K >> 5;

    float accM[4][4][4];
    uint32_t ch[4][4][2];
#pragma unroll
    for (int m = 0; m < 4; ++m)
#pragma unroll
        for (int n = 0; n < 4; ++n) {
#pragma unroll
            for (int e = 0; e < 4; ++e) accM[m][n][e] = 0.f;
            ch[m][n][0] = 0u; ch[m][n][1] = 0u;
        }

    auto load_stage = [&](int st, int k0) {
#pragma unroll
        for (int j = 0; j < 8; ++j) {
            const int q = j * 256 + tid;
            const int isB = q >> 10;
            const int sp = (q >> 9) & 1;
            const int row = (q >> 2) & 127;
            const int seg = q & 3;
            uint32_t rel = (uint32_t)(row * 128 + sp * 64 + seg * 16);
            rel ^= (rel >> 3) & 0x70;
            const uint32_t dst = sb + (uint32_t)st * STAGE_B + (uint32_t)isB * 16384 + rel;
            const __half* src;
            if (isB) src = (sp ? Bl : Bh) + (size_t)(bn + row) * K + k0 + seg * 8;
            else     src = (sp ? Al : Ah) + (size_t)(bm + row) * K + k0 + seg * 8;
            asm volatile("cp.async.cg.shared.global [%0], [%1], 16;" :: "r"(dst), "l"(src));
        }
    };

    auto compute_stage = [&](int st) {
        const uint32_t ab = sb + (uint32_t)st * STAGE_B;
        const uint32_t bb = ab + 16384;
#pragma unroll
        for (int kk = 0; kk < 2; ++kk) {
            uint32_t Af[4][4], Lf[4][4], Bf[4][2], Mf[4][2];
#pragma unroll
            for (int m = 0; m < 4; ++m) {
                const int row = wm * 64 + m * 16 + (lane & 15);
                const int colb = kk * 32 + ((lane >> 4) << 4);
                uint32_t r1 = (uint32_t)(row * 128 + colb);
                uint32_t r2 = (uint32_t)(row * 128 + 64 + colb);
                r1 ^= (r1 >> 3) & 0x70;
                r2 ^= (r2 >> 3) & 0x70;
                ldm4(Af[m], ab + r1);
                ldm4(Lf[m], ab + r2);
            }
#pragma unroll
            for (int p = 0; p < 2; ++p) {
                const int mm = lane >> 3;
                const int row = wn * 32 + p * 16 + ((mm >> 1) << 3) + (lane & 7);
                const int colb = kk * 32 + ((mm & 1) << 4);
                uint32_t r1 = (uint32_t)(row * 128 + colb);
                uint32_t r2 = (uint32_t)(row * 128 + 64 + colb);
                r1 ^= (r1 >> 3) & 0x70;
                r2 ^= (r2 >> 3) & 0x70;
                uint32_t t[4];
                ldm4(t, bb + r1);
                Bf[2 * p][0] = t[0]; Bf[2 * p][1] = t[1];
                Bf[2 * p + 1][0] = t[2]; Bf[2 * p + 1][1] = t[3];
                ldm4(t, bb + r2);
                Mf[2 * p][0] = t[0]; Mf[2 * p][1] = t[1];
                Mf[2 * p + 1][0] = t[2]; Mf[2 * p + 1][1] = t[3];
            }
#pragma unroll
            for (int m = 0; m < 4; ++m)
#pragma unroll
                for (int n = 0; n < 4; ++n) {
                    mma_f16(accM[m][n], Af[m], Bf[n]);
                    mma_f16acc(ch[m][n], Af[m], Mf[n]);
                    mma_f16acc(ch[m][n], Lf[m], Bf[n]);
                }
        }
        // spill fp16 cross accumulators into accM (scaled), reset window
#pragma unroll
        for (int m = 0; m < 4; ++m)
#pragma unroll
            for (int n = 0; n < 4; ++n) {
                const float2 p0 = __half22float2(*reinterpret_cast<__half2*>(&ch[m][n][0]));
                const float2 p1 = __half22float2(*reinterpret_cast<__half2*>(&ch[m][n][1]));
                accM[m][n][0] += p0.x * INV2048;
                accM[m][n][1] += p0.y * INV2048;
                accM[m][n][2] += p1.x * INV2048;
                accM[m][n][3] += p1.y * INV2048;
                ch[m][n][0] = 0u; ch[m][n][1] = 0u;
            }
    };

    for (int p = 0; p < 3; ++p) {
        if (p < niter) load_stage(p, p * 32);
        asm volatile("cp.async.commit_group;" ::: "memory");
    }
    for (int i = 0; i < niter; ++i) {
        asm volatile("cp.async.wait_group 2;" ::: "memory");
        __syncthreads();
        const int nxt = i + 3;
        if (nxt < niter) load_stage(nxt & (NSTAGE - 1), nxt * 32);
        asm volatile("cp.async.commit_group;" ::: "memory");
        compute_stage(i & (NSTAGE - 1));
    }
    asm volatile("cp.async.wait_group 0;" ::: "memory");

    // epilogue
    const int rb = bm + wm * 64 + (lane >> 2);
    const int cb = bn + wn * 32 + 2 * (lane & 3);
#pragma unroll
    for (int m = 0; m < 4; ++m) {
#pragma unroll
        for (int n = 0; n < 4; ++n) {
            const int cc = cb + n * 8;
            const float2 bi = *(const float2*)&bias[cc];
#pragma unroll
            for (int half = 0; half < 2; ++half) {
                const int r = rb + m * 16 + half * 8;
                if (r < Mreal) {
                    float v0 = accM[m][n][2 * half + 0] + bi.x;
                    float v1 = accM[m][n][2 * half + 1] + bi.y;
                    if (mode == 0) {
                        float2 o; o.x = v0; o.y = v1;
                        *(float2*)&C[(size_t)r * ldc + cc] = o;
                    } else {
                        v0 = fmaxf(v0, 0.f);
                        v1 = fmaxf(v1, 0.f);
                        __half h0, l0, h1, l1;
                        split2(v0, h0, l0);
                        split2(v1, h1, l1);
                        __half2 th; th.x = h0; th.y = h1;
                        __half2 tl; tl.x = l0; tl.y = l1;
                        *(__half2*)&Oh[(size_t)r * ldo + cc] = th;
                        *(__half2*)&Ol[(size_t)r * ldo + cc] = tl;
                    }
                }
            }
        }
    }
}

// ======================= HMMA GEMM (BN=64 — fills the chip for narrow N) =======================
#define STAGE_B64 24576
#define SMEM_GEMM64 (NSTAGE * STAGE_B64)

__global__ void __launch_bounds__(256, 1) hgemm64(
    const __half* __restrict__ Ah, const __half* __restrict__ Al,
    const __half* __restrict__ Bh, const __half* __restrict__ Bl,
    const float* __restrict__ bias, int K, int Mreal,
    float* __restrict__ C, int ldc)
{
    extern __shared__ __align__(16) char smem[];
    const uint32_t sb = s2u(smem);
    const int tid = threadIdx.x;
    const int lane = tid & 31, wid = tid >> 5;
    const int wm = wid & 1, wn = wid >> 1;           // warp tile: 64x16
    const int bm = blockIdx.y * 128, bn = blockIdx.x * 64;
    const int niter = K >> 5;

    float accM[4][2][4];
    uint32_t ch[4][2][2];
#pragma unroll
    for (int m = 0; m < 4; ++m)
#pragma unroll
        for (int n = 0; n < 2; ++n) {
#pragma unroll
            for (int e = 0; e < 4; ++e) accM[m][n][e] = 0.f;
            ch[m][n][0] = 0u; ch[m][n][1] = 0u;
        }

    auto load_stage = [&](int st, int k0) {
#pragma unroll
        for (int j = 0; j < 6; ++j) {
            const int q = j * 256 + tid;       // 0..1535
            const int isB = (q >= 1024);
            uint32_t dst;
            const __half* src;
            if (!isB) {
                const int sp = (q >> 9) & 1;
                const int row = (q >> 2) & 127;
                const int seg = q & 3;
                uint32_t rel = (uint32_t)(row * 128 + sp * 64 + seg * 16);
                rel ^= (rel >> 3) & 0x70;
                dst = sb + (uint32_t)st * STAGE_B64 + rel;
                src = (sp ? Al : Ah) + (size_t)(bm + row) * K + k0 + seg * 8;
            } else {
                const int u = q - 1024;        // 0..511
                const int sp = (u >> 8) & 1;
                const int row = (u >> 2) & 63;
                const int seg = u & 3;
                uint32_t rel = (uint32_t)(row * 128 + sp * 64 + seg * 16);
                rel ^= (rel >> 3) & 0x70;
                dst = sb + (uint32_t)st * STAGE_B64 + 16384 + rel;
                src = (sp ? Bl : Bh) + (size_t)(bn + row) * K + k0 + seg * 8;
            }
            asm volatile("cp.async.cg.shared.global [%0], [%1], 16;" :: "r"(dst), "l"(src));
        }
    };

    auto compute_stage = [&](int st) {
        const uint32_t ab = sb + (uint32_t)st * STAGE_B64;
        const uint32_t bb = ab + 16384;
#pragma unroll
        for (int kk = 0; kk < 2; ++kk) {
            uint32_t Af[4][4], Lf[4][4], Bf[2][2], Mf[2][2];
#pragma unroll
            for (int m = 0; m < 4; ++m) {
                const int row = wm * 64 + m * 16 + (lane & 15);
                const int colb = kk * 32 + ((lane >> 4) << 4);
                uint32_t r1 = (uint32_t)(row * 128 + colb);
                uint32_t r2 = (uint32_t)(row * 128 + 64 + colb);
                r1 ^= (r1 >> 3) & 0x70;
                r2 ^= (r2 >> 3) & 0x70;
                ldm4(Af[m], ab + r1);
                ldm4(Lf[m], ab + r2);
            }
            {
                const int mm = lane >> 3;
                const int row = wn * 16 + ((mm >> 1) << 3) + (lane & 7);
                const int colb = kk * 32 + ((mm & 1) << 4);
                uint32_t r1 = (uint32_t)(row * 128 + colb);
                uint32_t r2 = (uint32_t)(row * 128 + 64 + colb);
                r1 ^= (r1 >> 3) & 0x70;
                r2 ^= (r2 >> 3) & 0x70;
                uint32_t t[4];
                ldm4(t, bb + r1);
                Bf[0][0] = t[0]; Bf[0][1] = t[1];
                Bf[1][0] = t[2]; Bf[1][1] = t[3];
                ldm4(t, bb + r2);
                Mf[0][0] = t[0]; Mf[0][1] = t[1];
                Mf[1][0] = t[2]; Mf[1][1] = t[3];
            }
#pragma unroll
            for (int m = 0; m < 4; ++m)
#pragma unroll
                for (int n = 0; n < 2; ++n) {
                    mma_f16(accM[m][n], Af[m], Bf[n]);
                    mma_f16acc(ch[m][n], Af[m], Mf[n]);
                    mma_f16acc(ch[m][n], Lf[m], Bf[n]);
                }
        }
#pragma unroll
        for (int m = 0; m < 4; ++m)
#pragma unroll
            for (int n = 0; n < 2; ++n) {
                const float2 p0 = __half22float2(*reinterpret_cast<__half2*>(&ch[m][n][0]));
                const float2 p1 = __half22float2(*reinterpret_cast<__half2*>(&ch[m][n][1]));
                accM[m][n][0] += p0.x * INV2048;
                accM[m][n][1] += p0.y * INV2048;
                accM[m][n][2] += p1.x * INV2048;
                accM[m][n][3] += p1.y * INV2048;
                ch[m][n][0] = 0u; ch[m][n][1] = 0u;
            }
    };

    for (int p = 0; p < 3; ++p) {
        if (p < niter) load_stage(p, p * 32);
        asm volatile("cp.async.commit_group;" ::: "memory");
    }
    for (int i = 0; i < niter; ++i) {
        asm volatile("cp.async.wait_group 2;" ::: "memory");
        __syncthreads();
        const int nxt = i + 3;
        if (nxt < niter) load_stage(nxt & (NSTAGE - 1), nxt * 32);
        asm volatile("cp.async.commit_group;" ::: "memory");
        compute_stage(i & (NSTAGE - 1));
    }
    asm volatile("cp.async.wait_group 0;" ::: "memory");

    const int rb = bm + wm * 64 + (lane >> 2);
    const int cb = bn + wn * 16 + 2 * (lane & 3);
#pragma unroll
    for (int m = 0; m < 4; ++m) {
#pragma unroll
        for (int n = 0; n < 2; ++n) {
            const int cc = cb + n * 8;
            const float2 bi = *(const float2*)&bias[cc];
#pragma unroll
            for (int half = 0; half < 2; ++half) {
                const int r = rb + m * 16 + half * 8;
                if (r < Mreal) {
                    float2 o;
                    o.x = accM[m][n][2 * half + 0] + bi.x;
                    o.y = accM[m][n][2 * half + 1] + bi.y;
                    *(float2*)&C[(size_t)r * ldc + cc] = o;
                }
            }
        }
    }
}

// ======================= softmax =======================
__global__ void softmax_kernel() {
    const int n = blockIdx.x;
    const int lane = threadIdx.x;
    float v[3];
    float mx = -3.4e38f;
#pragma unroll
    for (int t = 0; t < 3; ++t) {
        const int i = lane + 32 * t;
        v[t] = (i < NCLS) ? g_comb[(size_t)n * NHEAD + i] : -3.4e38f;
        mx = fmaxf(mx, v[t]);
    }
#pragma unroll
    for (int s = 16; s > 0; s >>= 1) mx = fmaxf(mx, __shfl_xor_sync(0xffffffffu, mx, s));
    float sum = 0.f;
#pragma unroll
    for (int t = 0; t < 3; ++t) {
        const int i = lane + 32 * t;
        if (i < NCLS) { v[t] = expf(v[t] - mx); sum += v[t]; }
    }
#pragma unroll
    for (int s = 16; s > 0; s >>= 1) sum += __shfl_xor_sync(0xffffffffu, sum, s);
#pragma unroll
    for (int t = 0; t < 3; ++t) {
        const int i = lane + 32 * t;
        if (i < NCLS) g_scores[n * NCLS + i] = v[t] / sum;
    }
}

// ======================= per-class NMS =======================
#define CSMEM (4 * NPAD * 4 + NPAD * 8 + NPAD)

__global__ void __launch_bounds__(256) class_nms(
    const float* __restrict__ P, const int* __restrict__ imh, const int* __restrict__ imw)
{
    extern __shared__ __align__(16) char smemraw[];
    float* sx1 = (float*)smemraw;
    float* sy1 = sx1 + NPAD;
    float* sx2 = sy1 + NPAD;
    float* sy2 = sx2 + NPAD;
    unsigned long long* keys = (unsigned long long*)(sy2 + NPAD);
    char* alive = (char*)(keys + NPAD);
    __shared__ int s_nsurv;

    const int tid = threadIdx.x;
    const int cls = blockIdx.x;        // 0..89
    const int c = cls + 1;             // label
    const float Wim = (float)(*imw);
    const float Him = (float)(*imh);
    const float offv = (float)c * (fmaxf(Wim, Him) + 1.0f);

    if (tid == 0) s_nsurv = 0;

    for (int n = tid; n < NPAD; n += 256) {
        unsigned long long key = 0ull;
        if (n < N_ROIS) {
            float x1, y1, x2, y2;
            decode_one(n, c, P, Wim, Him, x1, y1, x2, y2);
            const float s = g_scores[n * NCLS + c];
            if (s > 0.05f && (x2 - x1) >= 0.01f && (y2 - y1) >= 0.01f) {
                sx1[n] = x1 + offv;
                sy1[n] = y1 + offv;
                sx2[n] = x2 + offv;
                sy2[n] = y2 + offv;
                key = ((unsigned long long)__float_as_uint(s) << 32)
                    | (unsigned long long)(0xFFFFFFFFu - (unsigned)n);
            }
        }
        keys[n] = key;
        alive[n] = 1;
    }
    __syncthreads();

    for (int k = 2; k <= NPAD; k <<= 1) {
        for (int j = k >> 1; j > 0; j >>= 1) {
            for (int i = tid; i < NPAD; i += 256) {
                const int l = i ^ j;
                if (l > i) {
                    const unsigned long long a = keys[i], b = keys[l];
                    const bool up = ((i & k) == 0);
                    if (up ? (a < b) : (a > b)) { keys[i] = b; keys[l] = a; }
                }
            }
            __syncthreads();
        }
    }

    for (int pos = 0; pos < NPAD; ++pos) {
        const unsigned long long k = keys[pos];
        if (k == 0ull) break;
        if (!alive[pos]) continue;
        if (s_nsurv >= MAXDET) break;
        const int ni = (int)(0xFFFFFFFFu - (unsigned)(k & 0xFFFFFFFFull));
        const float bx1 = sx1[ni], by1 = sy1[ni], bx2 = sx2[ni], by2 = sy2[ni];
        const float ai = (bx2 - bx1) * (by2 - by1);
        if (tid == 0) {
            const unsigned flat = (unsigned)(ni * NC1 + cls);
            g_surv[cls * MAXDET + s_nsurv] =
                (k & 0xFFFFFFFF00000000ull) | (unsigned long long)(0xFFFFFFFFu - flat);
            s_nsurv++;
        }
        for (int j = pos + 1 + tid; j < NPAD; j += 256) {
            if (!alive[j]) continue;
            const unsigned long long k2 = keys[j];
            if (k2 == 0ull) continue;
            const int nj = (int)(0xFFFFFFFFu - (unsigned)(k2 & 0xFFFFFFFFull));
            const float xx1 = fmaxf(bx1, sx1[nj]);
            const float yy1 = fmaxf(by1, sy1[nj]);
            const float xx2 = fminf(bx2, sx2[nj]);
            const float yy2 = fminf(by2, sy2[nj]);
            const float inter = fmaxf(xx2 - xx1, 0.f) * fmaxf(yy2 - yy1, 0.f);
            const float aj = (sx2[nj] - sx1[nj]) * (sy2[nj] - sy1[nj]);
            const float iou = inter / (ai + aj - inter + 1e-9f);
            if (iou > 0.5f) alive[j] = 0;
        }
        __syncthreads();
    }
    __syncthreads();
    if (tid == 0) g_snum[cls] = s_nsurv;
}

// ======================= merge + output =======================
__global__ void __launch_bounds__(128) final_select(
    const float* __restrict__ P, const int* __restrict__ imh, const int* __restrict__ imw,
    float* __restrict__ out, int out_size)
{
    __shared__ unsigned long long red[128];
    __shared__ int heads[NC1];
    __shared__ int cnts[NC1];
    __shared__ int keep[MAXDET];
    __shared__ int s_w;

    const int tid = threadIdx.x;
    if (tid < NC1) { heads[tid] = 0; cnts[tid] = g_snum[tid]; }
    if (tid < MAXDET) keep[tid] = -1;
    __syncthreads();

    for (int it = 0; it < MAXDET; ++it) {
        unsigned long long cand = 0ull;
        if (tid < NC1 && heads[tid] < cnts[tid])
            cand = g_surv[tid * MAXDET + heads[tid]];
        red[tid] = cand;
        __syncthreads();
        for (int s = 64; s > 0; s >>= 1) {
            if (tid < s) { if (red[tid + s] > red[tid]) red[tid] = red[tid + s]; }
            __syncthreads();
        }
        const unsigned long long best = red[0];
        if (best == 0ull) break;
        if (tid < NC1 && cand == best) s_w = tid;
        __syncthreads();
        if (tid == 0) {
            heads[s_w]++;
            keep[it] = (int)(0xFFFFFFFFu - (unsigned)(best & 0xFFFFFFFFull));
        }
        __syncthreads();
    }

    if (tid < MAXDET) {
        const int k = keep[tid];
        float b0 = 0, b1 = 0, b2 = 0, b3 = 0, s = 0, l = 0;
        if (k >= 0) {
            const int n = k / NC1;
            const int c = k % NC1 + 1;
            const float Wim = (float)(*imw);
            const float Him = (float)(*imh);
            float x1, y1, x2, y2;
            decode_one(n, c, P, Wim, Him, x1, y1, x2, y2);
            b0 = x1; b1 = y1; b2 = x2; b3 = y2;
            s = g_scores[n * NCLS + c];
            l = (float)c;
        }
        if (tid * 4 + 3 < out_size) {
            out[tid * 4 + 0] = b0;
            out[tid * 4 + 1] = b1;
            out[tid * 4 + 2] = b2;
            out[tid * 4 + 3] = b3;
        }
        if (4 * MAXDET + tid < out_size) out[4 * MAXDET + tid] = s;
        if (5 * MAXDET + tid < out_size) out[5 * MAXDET + tid] = l;
    }
}

// ======================= launch =======================
extern "C" void kernel_launch(void* const* d_in, const int* in_sizes, int n_in,
                              void* d_out, int out_size) {
    const float* X  = (const float*)d_in[0];
    const float* P  = (const float*)d_in[1];
    const float* W1 = (const float*)d_in[2];
    const float* b1 = (const float*)d_in[3];
    const float* W2 = (const float*)d_in[4];
    const float* b2 = (const float*)d_in[5];
    const float* Wc = (const float*)d_in[6];
    const float* bc = (const float*)d_in[7];
    const float* Wr = (const float*)d_in[8];
    const float* br = (const float*)d_in[9];
    const int* imh  = (const int*)d_in[10];
    const int* imw  = (const int*)d_in[11];

    __half *pAh, *pAl, *pW1h, *pW1l, *pW2h, *pW2l, *pWhh, *pWhl;
    __half *pH1h, *pH1l, *pH2h, *pH2l;
    float *pBiasH, *pComb;
    cudaGetSymbolAddress((void**)&pAh, gA_hi);
    cudaGetSymbolAddress((void**)&pAl, gA_lo);
    cudaGetSymbolAddress((void**)&pW1h, gW1_hi);
    cudaGetSymbolAddress((void**)&pW1l, gW1_lo);
    cudaGetSymbolAddress((void**)&pW2h, gW2_hi);
    cudaGetSymbolAddress((void**)&pW2l, gW2_lo);
    cudaGetSymbolAddress((void**)&pWhh, gWh_hi);
    cudaGetSymbolAddress((void**)&pWhl, gWh_lo);
    cudaGetSymbolAddress((void**)&pH1h, gH1_hi);
    cudaGetSymbolAddress((void**)&pH1l, gH1_lo);
    cudaGetSymbolAddress((void**)&pH2h, gH2_hi);
    cudaGetSymbolAddress((void**)&pH2l, gH2_lo);
    cudaGetSymbolAddress((void**)&pBiasH, gBiasH);
    cudaGetSymbolAddress((void**)&pComb, g_comb);

    cudaFuncSetAttribute(hgemm, cudaFuncAttributeMaxDynamicSharedMemorySize, SMEM_GEMM);
    cudaFuncSetAttribute(hgemm64, cudaFuncAttributeMaxDynamicSharedMemorySize, SMEM_GEMM64);
    cudaFuncSetAttribute(class_nms, cudaFuncAttributeMaxDynamicSharedMemorySize, CSMEM);

    // pre-pass
    split_X<<<(N_ROIS * IN_F / 4 + 255) / 256, 256>>>(X);
    tsplitW<<<dim3(IN_F / 32, REP / 32), dim3(32, 8)>>>(W1, pW1h, pW1l, IN_F, REP);
    tsplitW<<<dim3(REP / 32, REP / 32), dim3(32, 8)>>>(W2, pW2h, pW2l, REP, REP);
    build_head<<<dim3(NHEAD, REP / 256), 256>>>(Wc, Wr);
    build_bias<<<(NHEAD + 255) / 256, 256>>>(bc, br);

    // GEMM1: h1 = relu(X @ W1 + b1)
    hgemm<<<dim3(REP / 128, MPAD / 128), 256, SMEM_GEMM>>>(
        pAh, pAl, pW1h, pW1l, b1, IN_F, N_ROIS, 1, nullptr, 0, pH1h, pH1l, REP);
    // GEMM2: h2 = relu(h1 @ W2 + b2)
    hgemm<<<dim3(REP / 128, MPAD / 128), 256, SMEM_GEMM>>>(
        pH1h, pH1l, pW2h, pW2l, b2, REP, N_ROIS, 1, nullptr, 0, pH2h, pH2l, REP);
    // heads: comb = h2 @ [Wc|pad|Wr] + bias  (BN=64 -> 128 blocks, full chip)
    hgemm64<<<dim3(NHEAD / 64, MPAD / 128), 256, SMEM_GEMM64>>>(
        pH2h, pH2l, pWhh, pWhl, pBiasH, REP, N_ROIS, pComb, NHEAD);

    softmax_kernel<<<N_ROIS, 32>>>();
    class_nms<<<NC1, 256, CSMEM>>>(P, imh, imw);
    final_select<<<1, 128>>>(P, imh, imw, (float*)d_out, out_size);
}

// round 9
// speedup vs baseline: 1.1011x; 1.1011x over previous
#include <cuda_runtime.h>
#include <cuda_fp16.h>
#include <math.h>
#include <stdint.h>

#define N_ROIS 2000
#define MPAD   2048
#define IN_F   12544
#define REP    1024
#define NHEAD  512
#define NCLS   91
#define NC1    90
#define NPAD   2048
#define BBOX_CLIP_F 4.135166556742356f
#define MAXDET 100

// ======================= static scratch (no allocs) =======================
__device__ float gWhf[REP * NHEAD];        // combined head weight [K=REP][NHEAD]
__device__ float gBiasH[NHEAD];
__device__ float gH1f[MPAD * REP];
__device__ float gH2f[MPAD * REP];
__device__ float g_comb[N_ROIS * NHEAD];   // logits cols 0..90, breg cols 92+4c
__device__ float g_scores[N_ROIS * NCLS];
__device__ unsigned long long g_surv[NC1 * MAXDET];
__device__ int g_snum[NC1];

// ======================= helpers =======================
__device__ __forceinline__ uint32_t s2u(const void* p) {
    uint32_t a;
    asm("{ .reg .u64 t; cvta.to.shared.u64 t, %1; cvt.u32.u64 %0, t; }" : "=r"(a) : "l"(p));
    return a;
}
__device__ __forceinline__ void ldm4(uint32_t* r, uint32_t addr) {
    asm volatile("ldmatrix.sync.aligned.m8n8.x4.shared.b16 {%0,%1,%2,%3}, [%4];"
                 : "=r"(r[0]), "=r"(r[1]), "=r"(r[2]), "=r"(r[3]) : "r"(addr));
}
__device__ __forceinline__ void ldm4t(uint32_t* r, uint32_t addr) {
    asm volatile("ldmatrix.sync.aligned.m8n8.x4.trans.shared.b16 {%0,%1,%2,%3}, [%4];"
                 : "=r"(r[0]), "=r"(r[1]), "=r"(r[2]), "=r"(r[3]) : "r"(addr));
}
__device__ __forceinline__ void mma_f16(float* d, const uint32_t* a, const uint32_t* b) {
    asm volatile(
        "mma.sync.aligned.m16n8k16.row.col.f32.f16.f16.f32 "
        "{%0,%1,%2,%3}, {%4,%5,%6,%7}, {%8,%9}, {%0,%1,%2,%3};"
        : "+f"(d[0]), "+f"(d[1]), "+f"(d[2]), "+f"(d[3])
        : "r"(a[0]), "r"(a[1]), "r"(a[2]), "r"(a[3]), "r"(b[0]), "r"(b[1]));
}
// split x = h + l (l unscaled; subnormal loss ~2^-25 abs, negligible)
__device__ __forceinline__ void split2u(float x, __half& h, __half& l) {
    h = __float2half_rn(x);
    l = __float2half_rn(x - __half2float(h));
}
__device__ __forceinline__ uint32_t pack2(__half a, __half b) {
    __half2 t; t.x = a; t.y = b;
    return *reinterpret_cast<uint32_t*>(&t);
}
__device__ __forceinline__ void decode_one(
    int n, int c, const float* __restrict__ P, float Wim, float Him,
    float& x1, float& y1, float& x2, float& y2)
{
    const float4 p = *reinterpret_cast<const float4*>(&P[n * 4]);
    const float pw = p.z - p.x;
    const float ph = p.w - p.y;
    const float pcx = p.x + 0.5f * pw;
    const float pcy = p.y + 0.5f * ph;
    const float4 r = *reinterpret_cast<const float4*>(&g_comb[(size_t)n * NHEAD + 92 + c * 4]);
    const float dx = r.x / 10.0f;
    const float dy = r.y / 10.0f;
    const float dw = fminf(r.z / 5.0f, BBOX_CLIP_F);
    const float dh = fminf(r.w / 5.0f, BBOX_CLIP_F);
    const float cx = dx * pw + pcx;
    const float cy = dy * ph + pcy;
    const float w = expf(dw) * pw;
    const float hh = expf(dh) * ph;
    x1 = fminf(fmaxf(cx - 0.5f * w, 0.f), Wim);
    y1 = fminf(fmaxf(cy - 0.5f * hh, 0.f), Him);
    x2 = fminf(fmaxf(cx + 0.5f * w, 0.f), Wim);
    y2 = fminf(fmaxf(cy + 0.5f * hh, 0.f), Him);
}

// ======================= tiny pre-pass =======================
__global__ void build_headW(const float* __restrict__ Wc, const float* __restrict__ Wr) {
    const int idx = blockIdx.x * 256 + threadIdx.x;   // over REP*NHEAD
    const int k = idx >> 9;            // /NHEAD
    const int n = idx & (NHEAD - 1);
    float v = 0.f;
    if (n < NCLS) v = Wc[(size_t)k * NCLS + n];
    else if (n >= 92 && n < 92 + 4 * NCLS) v = Wr[(size_t)k * (4 * NCLS) + (n - 92)];
    gWhf[idx] = v;
}
__global__ void build_bias(const float* __restrict__ bc, const float* __restrict__ br) {
    const int c = blockIdx.x * 256 + threadIdx.x;
    if (c >= NHEAD) return;
    float v = 0.f;
    if (c < NCLS) v = bc[c];
    else if (c >= 92 && c < 92 + 4 * NCLS) v = br[c - 92];
    gBiasH[c] = v;
}

// ======================= fused-split HMMA GEMM =======================
// C[M,N] = A[M,K](fp32 row-major) @ B[K,N](fp32, n-contig), fp32-equivalent
// via in-kernel fp16 2-way split: acc += Ah*Bh + Ah*Bl + Al*Bh (one fp32 acc).
// A smem: [128 m][hi 64B | lo 64B]; B smem: k-major hi/lo tiles + ldmatrix.trans.
template <int BN>
__global__ void __launch_bounds__(256, 1) hgemmF(
    const float* __restrict__ A, const float* __restrict__ B,
    const float* __restrict__ bias, int K, int lda, int ldb,
    int Mreal, int relu, float* __restrict__ C, int ldc)
{
    constexpr int ROWB  = BN * 2;            // B split-tile row bytes
    constexpr int BTILE = 32 * ROWB;         // one B split tile
    constexpr int STG   = 16384 + 2 * BTILE; // stage bytes
    constexpr int BJ    = (BN == 128) ? 4 : 2;
    constexpr int NWN   = BN / 32;           // warps along N
    constexpr int MF    = BN / 32;           // m-frags per warp (= NWN; 8 warps tile 128 rows)

    extern __shared__ __align__(16) char smem[];
    const uint32_t sb = s2u(smem);
    const int tid = threadIdx.x;
    const int lane = tid & 31, wid = tid >> 5;
    const int wn = wid % NWN, wm = wid / NWN;
    const int wmbase = wm * (MF * 16);
    const int bm = blockIdx.y * 128, bn = blockIdx.x * BN;
    const int niter = K >> 5;

    float acc[MF][4][4];
#pragma unroll
    for (int m = 0; m < MF; ++m)
#pragma unroll
        for (int n = 0; n < 4; ++n)
#pragma unroll
            for (int e = 0; e < 4; ++e) acc[m][n][e] = 0.f;

    float4 aS[4];
    float4 bS[BJ];
    const int r0 = tid >> 3, seg = tid & 7;

    auto ldgA = [&](int i) {
        const int k0 = i * 32;
#pragma unroll
        for (int j = 0; j < 4; ++j) {
            const int gr = bm + r0 + 32 * j;
            if (gr < Mreal) aS[j] = *(const float4*)(A + (size_t)gr * lda + k0 + seg * 4);
            else aS[j] = make_float4(0.f, 0.f, 0.f, 0.f);
        }
    };
    auto ldgB = [&](int i) {
        const int k0 = i * 32;
#pragma unroll
        for (int j = 0; j < BJ; ++j) {
            const int nf = seg * 4 + j * 32;
            bS[j] = *(const float4*)(B + (size_t)(k0 + r0) * ldb + bn + nf);
        }
    };
    auto stsStage = [&](int i) {
        char* st = smem + (size_t)(i % 3) * STG;
        // A: rows r0+32j, k-floats seg*4..+3
#pragma unroll
        for (int j = 0; j < 4; ++j) {
            const int row = r0 + 32 * j;
            __half h0, l0, h1, l1, h2, l2, h3, l3;
            split2u(aS[j].x, h0, l0); split2u(aS[j].y, h1, l1);
            split2u(aS[j].z, h2, l2); split2u(aS[j].w, h3, l3);
            uint32_t relh = (uint32_t)(row * 128 + seg * 8);
            relh ^= (relh >> 3) & 0x70;
            uint32_t rell = (uint32_t)(row * 128 + 64 + seg * 8);
            rell ^= (rell >> 3) & 0x70;
            uint2 vh; vh.x = pack2(h0, h1); vh.y = pack2(h2, h3);
            uint2 vl; vl.x = pack2(l0, l1); vl.y = pack2(l2, l3);
            *(uint2*)(st + relh) = vh;
            *(uint2*)(st + rell) = vl;
        }
        // B: k-row r0, n-floats seg*4 + j*32
#pragma unroll
        for (int j = 0; j < BJ; ++j) {
            const int nf = seg * 4 + j * 32;
            __half h0, l0, h1, l1, h2, l2, h3, l3;
            split2u(bS[j].x, h0, l0); split2u(bS[j].y, h1, l1);
            split2u(bS[j].z, h2, l2); split2u(bS[j].w, h3, l3);
            uint32_t rel = (uint32_t)(r0 * ROWB + nf * 2);
            if (BN == 128) rel ^= ((rel >> 8) & 7) << 4;
            else           rel ^= ((rel >> 7) & 7) << 4;
            uint2 vh; vh.x = pack2(h0, h1); vh.y = pack2(h2, h3);
            uint2 vl; vl.x = pack2(l0, l1); vl.y = pack2(l2, l3);
            *(uint2*)(st + 16384 + rel) = vh;
            *(uint2*)(st + 16384 + BTILE + rel) = vl;
        }
    };
    auto compute = [&](int i) {
        const uint32_t ab = sb + (uint32_t)(i % 3) * STG;
        const uint32_t bb = ab + 16384;
#pragma unroll
        for (int kk = 0; kk < 2; ++kk) {
            uint32_t Af[MF][4], Lf[MF][4], Bf[4][2], Mf[4][2];
#pragma unroll
            for (int m = 0; m < MF; ++m) {
                const int row = wmbase + m * 16 + (lane & 15);
                const int colb = kk * 32 + ((lane >> 4) << 4);
                uint32_t rr1 = (uint32_t)(row * 128 + colb);
                uint32_t rr2 = (uint32_t)(row * 128 + 64 + colb);
                rr1 ^= (rr1 >> 3) & 0x70;
                rr2 ^= (rr2 >> 3) & 0x70;
                ldm4(Af[m], ab + rr1);
                ldm4(Lf[m], ab + rr2);
            }
#pragma unroll
            for (int p = 0; p < 2; ++p) {
                const int grp = lane >> 3, kr = lane & 7;
                const int kx = kk * 16 + (grp & 1) * 8 + kr;
                const int nb = wn * 32 + p * 16 + (grp >> 1) * 8;
                uint32_t rel = (uint32_t)(kx * ROWB + nb * 2);
                if (BN == 128) rel ^= ((rel >> 8) & 7) << 4;
                else           rel ^= ((rel >> 7) & 7) << 4;
                uint32_t t[4];
                ldm4t(t, bb + rel);
                Bf[2 * p][0] = t[0]; Bf[2 * p][1] = t[1];
                Bf[2 * p + 1][0] = t[2]; Bf[2 * p + 1][1] = t[3];
                ldm4t(t, bb + BTILE + rel);
                Mf[2 * p][0] = t[0]; Mf[2 * p][1] = t[1];
                Mf[2 * p + 1][0] = t[2]; Mf[2 * p + 1][1] = t[3];
            }
#pragma unroll
            for (int m = 0; m < MF; ++m)
#pragma unroll
                for (int n = 0; n < 4; ++n) {
                    mma_f16(acc[m][n], Af[m], Bf[n]);
                    mma_f16(acc[m][n], Af[m], Mf[n]);
                    mma_f16(acc[m][n], Lf[m], Bf[n]);
                }
        }
    };

    // pipeline: 3 smem buffers, register staging one stage ahead
    ldgA(0); ldgB(0);
    stsStage(0);
    if (niter > 1) { ldgA(1); ldgB(1); }
    __syncthreads();
    for (int i = 0; i < niter; ++i) {
        if (i + 1 < niter) stsStage(i + 1);
        if (i + 2 < niter) { ldgA(i + 2); ldgB(i + 2); }
        __syncthreads();
        compute(i);
    }

    // epilogue
    const int rb = bm + wmbase + (lane >> 2);
    const int cb = bn + wn * 32 + 2 * (lane & 3);
#pragma unroll
    for (int m = 0; m < MF; ++m) {
#pragma unroll
        for (int n = 0; n < 4; ++n) {
            const int cc = cb + n * 8;
            const float2 bi = *(const float2*)&bias[cc];
#pragma unroll
            for (int hf = 0; hf < 2; ++hf) {
                const int r = rb + m * 16 + hf * 8;
                if (r < Mreal) {
                    float v0 = acc[m][n][2 * hf + 0] + bi.x;
                    float v1 = acc[m][n][2 * hf + 1] + bi.y;
                    if (relu) { v0 = fmaxf(v0, 0.f); v1 = fmaxf(v1, 0.f); }
                    float2 o; o.x = v0; o.y = v1;
                    *(float2*)&C[(size_t)r * ldc + cc] = o;
                }
            }
        }
    }
}

// ======================= softmax =======================
__global__ void softmax_kernel() {
    const int n = blockIdx.x;
    const int lane = threadIdx.x;
    float v[3];
    float mx = -3.4e38f;
#pragma unroll
    for (int t = 0; t < 3; ++t) {
        const int i = lane + 32 * t;
        v[t] = (i < NCLS) ? g_comb[(size_t)n * NHEAD + i] : -3.4e38f;
        mx = fmaxf(mx, v[t]);
    }
#pragma unroll
    for (int s = 16; s > 0; s >>= 1) mx = fmaxf(mx, __shfl_xor_sync(0xffffffffu, mx, s));
    float sum = 0.f;
#pragma unroll
    for (int t = 0; t < 3; ++t) {
        const int i = lane + 32 * t;
        if (i < NCLS) { v[t] = expf(v[t] - mx); sum += v[t]; }
    }
#pragma unroll
    for (int s = 16; s > 0; s >>= 1) sum += __shfl_xor_sync(0xffffffffu, sum, s);
#pragma unroll
    for (int t = 0; t < 3; ++t) {
        const int i = lane + 32 * t;
        if (i < NCLS) g_scores[n * NCLS + i] = v[t] / sum;
    }
}

// ======================= per-class NMS =======================
#define CSMEM (4 * NPAD * 4 + NPAD * 8 + NPAD)

__global__ void __launch_bounds__(256) class_nms(
    const float* __restrict__ P, const int* __restrict__ imh, const int* __restrict__ imw)
{
    extern __shared__ __align__(16) char smemraw[];
    float* sx1 = (float*)smemraw;
    float* sy1 = sx1 + NPAD;
    float* sx2 = sy1 + NPAD;
    float* sy2 = sx2 + NPAD;
    unsigned long long* keys = (unsigned long long*)(sy2 + NPAD);
    char* alive = (char*)(keys + NPAD);
    __shared__ int s_nsurv;

    const int tid = threadIdx.x;
    const int cls = blockIdx.x;
    const int c = cls + 1;
    const float Wim = (float)(*imw);
    const float Him = (float)(*imh);
    const float offv = (float)c * (fmaxf(Wim, Him) + 1.0f);

    if (tid == 0) s_nsurv = 0;

    for (int n = tid; n < NPAD; n += 256) {
        unsigned long long key = 0ull;
        if (n < N_ROIS) {
            float x1, y1, x2, y2;
            decode_one(n, c, P, Wim, Him, x1, y1, x2, y2);
            const float s = g_scores[n * NCLS + c];
            if (s > 0.05f && (x2 - x1) >= 0.01f && (y2 - y1) >= 0.01f) {
                sx1[n] = x1 + offv;
                sy1[n] = y1 + offv;
                sx2[n] = x2 + offv;
                sy2[n] = y2 + offv;
                key = ((unsigned long long)__float_as_uint(s) << 32)
                    | (unsigned long long)(0xFFFFFFFFu - (unsigned)n);
            }
        }
        keys[n] = key;
        alive[n] = 1;
    }
    __syncthreads();

    for (int k = 2; k <= NPAD; k <<= 1) {
        for (int j = k >> 1; j > 0; j >>= 1) {
            for (int i = tid; i < NPAD; i += 256) {
                const int l = i ^ j;
                if (l > i) {
                    const unsigned long long a = keys[i], b = keys[l];
                    const bool up = ((i & k) == 0);
                    if (up ? (a < b) : (a > b)) { keys[i] = b; keys[l] = a; }
                }
            }
            __syncthreads();
        }
    }

    for (int pos = 0; pos < NPAD; ++pos) {
        const unsigned long long k = keys[pos];
        if (k == 0ull) break;
        if (!alive[pos]) continue;
        if (s_nsurv >= MAXDET) break;
        const int ni = (int)(0xFFFFFFFFu - (unsigned)(k & 0xFFFFFFFFull));
        const float bx1 = sx1[ni], by1 = sy1[ni], bx2 = sx2[ni], by2 = sy2[ni];
        const float ai = (bx2 - bx1) * (by2 - by1);
        if (tid == 0) {
            const unsigned flat = (unsigned)(ni * NC1 + cls);
            g_surv[cls * MAXDET + s_nsurv] =
                (k & 0xFFFFFFFF00000000ull) | (unsigned long long)(0xFFFFFFFFu - flat);
            s_nsurv++;
        }
        for (int j = pos + 1 + tid; j < NPAD; j += 256) {
            if (!alive[j]) continue;
            const unsigned long long k2 = keys[j];
            if (k2 == 0ull) continue;
            const int nj = (int)(0xFFFFFFFFu - (unsigned)(k2 & 0xFFFFFFFFull));
            const float xx1 = fmaxf(bx1, sx1[nj]);
            const float yy1 = fmaxf(by1, sy1[nj]);
            const float xx2 = fminf(bx2, sx2[nj]);
            const float yy2 = fminf(by2, sy2[nj]);
            const float inter = fmaxf(xx2 - xx1, 0.f) * fmaxf(yy2 - yy1, 0.f);
            const float aj = (sx2[nj] - sx1[nj]) * (sy2[nj] - sy1[nj]);
            const float iou = inter / (ai + aj - inter + 1e-9f);
            if (iou > 0.5f) alive[j] = 0;
        }
        __syncthreads();
    }
    __syncthreads();
    if (tid == 0) g_snum[cls] = s_nsurv;
}

// ======================= merge + output =======================
__global__ void __launch_bounds__(128) final_select(
    const float* __restrict__ P, const int* __restrict__ imh, const int* __restrict__ imw,
    float* __restrict__ out, int out_size)
{
    __shared__ unsigned long long red[128];
    __shared__ int heads[NC1];
    __shared__ int cnts[NC1];
    __shared__ int keep[MAXDET];
    __shared__ int s_w;

    const int tid = threadIdx.x;
    if (tid < NC1) { heads[tid] = 0; cnts[tid] = g_snum[tid]; }
    if (tid < MAXDET) keep[tid] = -1;
    __syncthreads();

    for (int it = 0; it < MAXDET; ++it) {
        unsigned long long cand = 0ull;
        if (tid < NC1 && heads[tid] < cnts[tid])
            cand = g_surv[tid * MAXDET + heads[tid]];
        red[tid] = cand;
        __syncthreads();
        for (int s = 64; s > 0; s >>= 1) {
            if (tid < s) { if (red[tid + s] > red[tid]) red[tid] = red[tid + s]; }
            __syncthreads();
        }
        const unsigned long long best = red[0];
        if (best == 0ull) break;
        if (tid < NC1 && cand == best) s_w = tid;
        __syncthreads();
        if (tid == 0) {
            heads[s_w]++;
            keep[it] = (int)(0xFFFFFFFFu - (unsigned)(best & 0xFFFFFFFFull));
        }
        __syncthreads();
    }

    if (tid < MAXDET) {
        const int k = keep[tid];
        float b0 = 0, b1 = 0, b2 = 0, b3 = 0, s = 0, l = 0;
        if (k >= 0) {
            const int n = k / NC1;
            const int c = k % NC1 + 1;
            const float Wim = (float)(*imw);
            const float Him = (float)(*imh);
            float x1, y1, x2, y2;
            decode_one(n, c, P, Wim, Him, x1, y1, x2, y2);
            b0 = x1; b1 = y1; b2 = x2; b3 = y2;
            s = g_scores[n * NCLS + c];
            l = (float)c;
        }
        if (tid * 4 + 3 < out_size) {
            out[tid * 4 + 0] = b0;
            out[tid * 4 + 1] = b1;
            out[tid * 4 + 2] = b2;
            out[tid * 4 + 3] = b3;
        }
        if (4 * MAXDET + tid < out_size) out[4 * MAXDET + tid] = s;
        if (5 * MAXDET + tid < out_size) out[5 * MAXDET + tid] = l;
    }
}

// ======================= launch =======================
extern "C" void kernel_launch(void* const* d_in, const int* in_sizes, int n_in,
                              void* d_out, int out_size) {
    const float* X  = (const float*)d_in[0];
    const float* P  = (const float*)d_in[1];
    const float* W1 = (const float*)d_in[2];
    const float* b1 = (const float*)d_in[3];
    const float* W2 = (const float*)d_in[4];
    const float* b2 = (const float*)d_in[5];
    const float* Wc = (const float*)d_in[6];
    const float* bc = (const float*)d_in[7];
    const float* Wr = (const float*)d_in[8];
    const float* br = (const float*)d_in[9];
    const int* imh  = (const int*)d_in[10];
    const int* imw  = (const int*)d_in[11];

    float *pWh, *pBiasH, *pH1, *pH2, *pComb;
    cudaGetSymbolAddress((void**)&pWh, gWhf);
    cudaGetSymbolAddress((void**)&pBiasH, gBiasH);
    cudaGetSymbolAddress((void**)&pH1, gH1f);
    cudaGetSymbolAddress((void**)&pH2, gH2f);
    cudaGetSymbolAddress((void**)&pComb, g_comb);

    const int SMEM128 = 3 * (16384 + 2 * (32 * 256));   // 98304
    const int SMEM64  = 3 * (16384 + 2 * (32 * 128));   // 73728
    cudaFuncSetAttribute(hgemmF<128>, cudaFuncAttributeMaxDynamicSharedMemorySize, SMEM128);
    cudaFuncSetAttribute(hgemmF<64>,  cudaFuncAttributeMaxDynamicSharedMemorySize, SMEM64);
    cudaFuncSetAttribute(class_nms, cudaFuncAttributeMaxDynamicSharedMemorySize, CSMEM);

    // tiny pre-pass (head weight gather only)
    build_headW<<<REP * NHEAD / 256, 256>>>(Wc, Wr);
    build_bias<<<(NHEAD + 255) / 256, 256>>>(bc, br);

    // GEMM1: h1 = relu(X @ W1 + b1)
    hgemmF<128><<<dim3(REP / 128, MPAD / 128), 256, SMEM128>>>(
        X, W1, b1, IN_F, IN_F, REP, N_ROIS, 1, pH1, REP);
    // GEMM2: h2 = relu(h1 @ W2 + b2)
    hgemmF<128><<<dim3(REP / 128, MPAD / 128), 256, SMEM128>>>(
        pH1, W2, b2, REP, REP, REP, N_ROIS, 1, pH2, REP);
    // heads: comb = h2 @ Wh + biasH  (BN=64 -> 128 CTAs)
    hgemmF<64><<<dim3(NHEAD / 64, MPAD / 128), 256, SMEM64>>>(
        pH2, pWh, pBiasH, REP, REP, NHEAD, N_ROIS, 0, pComb, NHEAD);

    softmax_kernel<<<N_ROIS, 32>>>();
    class_nms<<<NC1, 256, CSMEM>>>(P, imh, imw);
    final_select<<<1, 128>>>(P, imh, imw, (float*)d_out, out_size);
}